// round 6
// baseline (speedup 1.0000x reference)
#include <cuda_runtime.h>
#include <cuda_bf16.h>

#define T_SEQ   256
#define HID     128
#define BATCH   1024
#define VOCABN  60
#define NCTA    152
#define RPG     4
#define FC_RPB  16

// ---------------- device scratch ----------------
__device__ float g_last[BATCH * HID];
__device__ int   g_perm[BATCH];          // rows sorted by length (ascending)

#define FMA2(acc, a, b) \
    asm("fma.rn.f32x2 %0, %1, %2, %0;" : "+l"(acc) : "l"(a), "l"(b))
#define ADD2(dst, a, b) \
    asm("add.rn.f32x2 %0, %1, %2;" : "=l"(dst) : "l"(a), "l"(b))
#define UNPACK2(lo, hi, v) \
    asm("mov.b64 {%0,%1}, %2;" : "=f"(lo), "=f"(hi) : "l"(v))

__device__ __forceinline__ float tanh_fast(float z) {
    float e = __expf(2.0f * z);
    return 1.0f - __fdividef(2.0f, e + 1.0f);
}

// ---------------- kernel 1: counting sort of rows by length ----------------
__global__ __launch_bounds__(1024) void sort_kernel(const int* __restrict__ lengths) {
    __shared__ int hist[257];
    __shared__ int scan[257];
    __shared__ int cnt[257];
    int tid = threadIdx.x;
    if (tid < 257) hist[tid] = 0;
    __syncthreads();
    atomicAdd(&hist[lengths[tid]], 1);     // len in [1,256]
    __syncthreads();
    if (tid <= 256) scan[tid] = hist[tid];
    __syncthreads();
    for (int d = 1; d <= 256; d <<= 1) {
        int val = 0;
        if (tid <= 256 && tid >= d) val = scan[tid - d];
        __syncthreads();
        if (tid <= 256) scan[tid] += val;
        __syncthreads();
    }
    if (tid <= 256) cnt[tid] = (tid == 0) ? 0 : scan[tid - 1];
    __syncthreads();
    int p = atomicAdd(&cnt[lengths[tid]], 1);
    g_perm[p] = tid;
}

// ---------------- kernel 2: main RNN ----------------
// 152 CTAs x 256 threads (2 groups of 128). Group processes one QUAD of 4
// sorted-adjacent (= similar length) rows, branch-free, to the quad max len.
// Thread j holds W row j in 64 packed f32x2 regs; h via broadcast LDS.128.
// P = emb @ W_ih^T computed in-CTA (2 waves, in place in shP).
__global__ __launch_bounds__(256, 1) void rnn_main(
    const int* __restrict__ x, const int* __restrict__ lengths,
    const float* __restrict__ W_hh,
    const float* __restrict__ emb, const float* __restrict__ W_ih)
{
    __shared__ float shP[VOCABN * HID];                       // emb staging, then P (30 KB)
    __shared__ __align__(16) float sh_h[2][RPG][2][HID];      // 8 KB
    __shared__ int sh_tok[2][RPG][T_SEQ];                     // 8 KB

    int tid = threadIdx.x;
    int g   = tid >> 7;
    int j   = tid & 127;
    int c   = blockIdx.x;

    // quad assignment: singles (c>=104) take the 48 longest quads (asc 208..255);
    // doubles (c<104) pair quads (207-c, c) -> per-CTA step sum == 207.
    int asc;
    if (c >= 104) asc = (g == 0) ? (359 - c) : -1;
    else          asc = (g == 0) ? (207 - c) : c;

    int row[RPG], lend[RPG];
    int L = 0;
    if (asc >= 0) {
#pragma unroll
        for (int s = 0; s < RPG; s++) {
            row[s]  = g_perm[4 * asc + s];
            lend[s] = lengths[row[s]] - 1;
        }
        L = lend[RPG - 1] + 1;            // ascending within quad -> last is max
#pragma unroll
        for (int s = 0; s < RPG; s++) {
            sh_tok[g][s][j]       = x[row[s] * T_SEQ + j];
            sh_tok[g][s][j + 128] = x[row[s] * T_SEQ + 128 + j];
            sh_h[g][s][0][j] = 0.0f;
        }
    }

    // stage emb into shP
    for (int i = tid; i < VOCABN * HID; i += 256) shP[i] = emb[i];

    // W_ih row j -> w registers; compute P in 2 waves (in place)
    unsigned long long w[64];
    {
        const ulonglong2* Wq = reinterpret_cast<const ulonglong2*>(W_ih) + (size_t)j * 32;
#pragma unroll
        for (int i = 0; i < 32; i++) { ulonglong2 tq = Wq[i]; w[2*i] = tq.x; w[2*i+1] = tq.y; }
    }
    __syncthreads();
#pragma unroll 1
    for (int wave = 0; wave < 2; wave++) {
        float pv[15];
        int v0 = g * 30 + wave * 15;
#pragma unroll 1
        for (int vi = 0; vi < 15; vi++) {
            const ulonglong2* eq =
                reinterpret_cast<const ulonglong2*>(&shP[(v0 + vi) * HID]);
            unsigned long long a0 = 0ull, a1 = 0ull, a2 = 0ull, a3 = 0ull;
#pragma unroll
            for (int i = 0; i < 32; i += 2) {
                ulonglong2 e0 = eq[i];
                ulonglong2 e1 = eq[i + 1];
                FMA2(a0, w[2 * i + 0], e0.x);
                FMA2(a1, w[2 * i + 1], e0.y);
                FMA2(a2, w[2 * i + 2], e1.x);
                FMA2(a3, w[2 * i + 3], e1.y);
            }
            ADD2(a0, a0, a1); ADD2(a2, a2, a3); ADD2(a0, a0, a2);
            float lo, hi; UNPACK2(lo, hi, a0);
            pv[vi] = lo + hi;
        }
        __syncthreads();                       // all emb reads of this wave done
#pragma unroll
        for (int vi = 0; vi < 15; vi++) shP[(v0 + vi) * HID + j] = pv[vi];
        __syncthreads();                       // P rows visible (wave2 reads others)
    }

    // reload w <- W_hh row j
    {
        const ulonglong2* Wq = reinterpret_cast<const ulonglong2*>(W_hh) + (size_t)j * 32;
#pragma unroll
        for (int i = 0; i < 32; i++) { ulonglong2 tq = Wq[i]; w[2*i] = tq.x; w[2*i+1] = tq.y; }
    }

    // main loop: branch-free 4-row body, per-group named barrier
    for (int t = 0; t < L; t++) {
        int cur = t & 1, nxt = cur ^ 1;
#pragma unroll
        for (int s = 0; s < RPG; s++) {
            int tok   = sh_tok[g][s][t];
            float base = shP[tok * HID + j];
            const ulonglong2* hq =
                reinterpret_cast<const ulonglong2*>(sh_h[g][s][cur]);
            unsigned long long a0 = 0ull, a1 = 0ull, a2 = 0ull, a3 = 0ull;
#pragma unroll
            for (int i = 0; i < 32; i += 2) {
                ulonglong2 v0 = hq[i];
                ulonglong2 v1 = hq[i + 1];
                FMA2(a0, w[2 * i + 0], v0.x);
                FMA2(a1, w[2 * i + 1], v0.y);
                FMA2(a2, w[2 * i + 2], v1.x);
                FMA2(a3, w[2 * i + 3], v1.y);
            }
            ADD2(a0, a0, a1); ADD2(a2, a2, a3); ADD2(a0, a0, a2);
            float lo, hi; UNPACK2(lo, hi, a0);
            float h = tanh_fast(base + lo + hi);
            sh_h[g][s][nxt][j] = h;
            if (t == lend[s])                       // predicated STG, no branch
                g_last[row[s] * HID + j] = h;
        }
        asm volatile("bar.sync %0, 128;" :: "r"(g + 1) : "memory");
    }
}

// ---------------- kernel 3: out = h_last @ W_fc^T + b_fc ----------------
__global__ __launch_bounds__(256) void fc_kernel(
    const float* __restrict__ W_fc, const float* __restrict__ b_fc,
    float* __restrict__ out)
{
    __shared__ __align__(16) float sW[VOCABN][HID + 4];
    __shared__ __align__(16) float sH[FC_RPB][HID + 4];
    int tid = threadIdx.x;
    int b0  = blockIdx.x * FC_RPB;

    for (int i = tid; i < VOCABN * HID; i += 256) sW[i / HID][i % HID] = W_fc[i];
    for (int i = tid; i < FC_RPB * HID; i += 256) sH[i / HID][i % HID] = g_last[(size_t)b0 * HID + i];
    __syncthreads();

    int v  = tid >> 2;
    int bq = tid & 3;
    if (v < VOCABN) {
        float acc0 = 0.f, acc1 = 0.f, acc2 = 0.f, acc3 = 0.f;
#pragma unroll
        for (int k = 0; k < HID; k += 4) {
            float4 wv = *reinterpret_cast<const float4*>(&sW[v][k]);
            float4 h0 = *reinterpret_cast<const float4*>(&sH[bq * 4 + 0][k]);
            float4 h1 = *reinterpret_cast<const float4*>(&sH[bq * 4 + 1][k]);
            float4 h2 = *reinterpret_cast<const float4*>(&sH[bq * 4 + 2][k]);
            float4 h3 = *reinterpret_cast<const float4*>(&sH[bq * 4 + 3][k]);
            acc0 += wv.x * h0.x + wv.y * h0.y + wv.z * h0.z + wv.w * h0.w;
            acc1 += wv.x * h1.x + wv.y * h1.y + wv.z * h1.z + wv.w * h1.w;
            acc2 += wv.x * h2.x + wv.y * h2.y + wv.z * h2.z + wv.w * h2.w;
            acc3 += wv.x * h3.x + wv.y * h3.y + wv.z * h3.z + wv.w * h3.w;
        }
        float bias = b_fc[v];
        out[(size_t)(b0 + bq * 4 + 0) * VOCABN + v] = acc0 + bias;
        out[(size_t)(b0 + bq * 4 + 1) * VOCABN + v] = acc1 + bias;
        out[(size_t)(b0 + bq * 4 + 2) * VOCABN + v] = acc2 + bias;
        out[(size_t)(b0 + bq * 4 + 3) * VOCABN + v] = acc3 + bias;
    }
}

// ---------------- launch ----------------
extern "C" void kernel_launch(void* const* d_in, const int* in_sizes, int n_in,
                              void* d_out, int out_size) {
    const int*   x       = (const int*)d_in[0];
    const int*   lengths = (const int*)d_in[1];
    const float* emb     = (const float*)d_in[2];
    const float* W_ih    = (const float*)d_in[3];
    const float* W_hh    = (const float*)d_in[4];
    const float* W_fc    = (const float*)d_in[5];
    const float* b_fc    = (const float*)d_in[6];
    float*       out     = (float*)d_out;

    sort_kernel<<<1, 1024>>>(lengths);
    rnn_main<<<NCTA, 256>>>(x, lengths, W_hh, emb, W_ih);
    fc_kernel<<<BATCH / FC_RPB, 256>>>(W_fc, b_fc, out);
}